// round 16
// baseline (speedup 1.0000x reference)
#include <cuda_runtime.h>
#include <math.h>

// Problem constants
#define BATCH   4096
#define VOCABSZ 100000
#define EMBDIM  64
#define D_IN    256
#define D_H     256
#define D_OUT   128
#define N_NEG4  4

// Scratch: NORMALIZED tower outputs (u then v)
__device__ float g_uv[2u * BATCH * D_OUT];
// Device-wide barrier ticket counter (monotone across launches; no reset needed)
__device__ unsigned g_bar = 0u;

// Tiling
constexpr int TM    = 64;    // rows per block
constexpr int XSTR  = 260;   // X/H smem row stride (floats): conflict-free fragment loads
constexpr int W1STR = 264;   // W1 tile stride
constexpr int W2STR = 136;   // W2 tile stride
constexpr int USTR  = 129;   // U staging stride
constexpr int XS_FLOATS   = TM * XSTR;            // 16640
constexpr int WBUF_FLOATS = 32 * W1STR;           // 8448
constexpr int SMEM_FLOATS = XS_FLOATS + 2 * WBUF_FLOATS;   // 134144 B
// NOTE: 134 KB smem => exactly 1 CTA/SM; grid=128 <= 148 SMs => all CTAs
// co-resident => device-wide spin barrier is deadlock-free.

__device__ __forceinline__ unsigned f2tf32(float f) {
    unsigned r; asm("cvt.rna.tf32.f32 %0, %1;" : "=r"(r) : "f"(f)); return r;
}
__device__ __forceinline__ float tf32f(float f) { return __uint_as_float(f2tf32(f)); }

#define MMA_TF32(c, a, b0, b1)                                              \
    asm volatile("mma.sync.aligned.m16n8k8.row.col.f32.tf32.tf32.f32 "      \
        "{%0,%1,%2,%3}, {%4,%5,%6,%7}, {%8,%9}, {%0,%1,%2,%3};"             \
        : "+f"((c)[0]), "+f"((c)[1]), "+f"((c)[2]), "+f"((c)[3])            \
        : "r"((a)[0]), "r"((a)[1]), "r"((a)[2]), "r"((a)[3]),               \
          "r"(b0), "r"(b1))

__device__ __forceinline__ void cp16(float* s, const float* g) {
    unsigned saddr = (unsigned)__cvta_generic_to_shared(s);
    asm volatile("cp.async.cg.shared.global [%0], [%1], 16;" :: "r"(saddr), "l"(g));
}
#define CP_COMMIT()   asm volatile("cp.async.commit_group;" ::: "memory")
#define CP_WAIT_ALL() asm volatile("cp.async.wait_group 0;" ::: "memory")

__global__ __launch_bounds__(512, 1)
void fused_kernel(const int* __restrict__ user_ids, const int* __restrict__ item_ids,
                  const float* __restrict__ user_tables, const float* __restrict__ item_tables,
                  const float* __restrict__ uW1, const float* __restrict__ ub1,
                  const float* __restrict__ uW2, const float* __restrict__ ub2,
                  const float* __restrict__ iW1, const float* __restrict__ ib1,
                  const float* __restrict__ iW2, const float* __restrict__ ib2,
                  const int* __restrict__ sw_ids, const float* __restrict__ sw_table,
                  float* __restrict__ out)
{
    extern __shared__ float smem[];
    float* Xs  = smem;                 // X then H, [64][XSTR], tf32 bit patterns
    float* Wb0 = smem + XS_FLOATS;     // W tile double buffers / U staging
    float* Wb1 = Wb0 + WBUF_FLOATS;

    const int tower  = blockIdx.x >> 6;
    const int rowblk = blockIdx.x & 63;

    const int*   ids = tower ? item_ids    : user_ids;
    const float* tbl = tower ? item_tables : user_tables;
    const float* W1  = tower ? iW1 : uW1;
    const float* b1  = tower ? ib1 : ub1;
    const float* W2  = tower ? iW2 : uW2;
    const float* b2  = tower ? ib2 : ub2;
    float* gout = g_uv + (size_t)tower * BATCH * D_OUT;

    const int tid  = threadIdx.x;      // 512 threads = 16 warps
    const int warp = tid >> 5;
    const int lane = tid & 31;
    const int g    = lane >> 2;        // 0..7
    const int t4   = lane & 3;         // 0..3
    const int w8    = warp & 7;        // n-split within half
    const int mbase = (warp >> 3) * 32;  // m-split: warps 0-7 rows 0-31, 8-15 rows 32-63
    const int row0 = rowblk * TM;

    // ---- Prologue: launch W1 tile 0 (32x256) into Wb0 ----
    #pragma unroll
    for (int i = tid; i < 32 * 64; i += 512) {
        int kr = i >> 6, f4 = (i & 63) << 2;
        cp16(&Wb0[kr * W1STR + f4], &W1[kr * 256 + f4]);
    }
    CP_COMMIT();

    // ---- Embedding gather: ids to registers first (MLP), then independent table LDGs ----
    {
        const int c    = tid & 255;
        const int half = tid >> 8;                     // 0 or 1
        const int f = c >> 6, e = c & 63;
        const float* tf = tbl + (size_t)f * VOCABSZ * EMBDIM + e;
        const int* idp = ids + f;
        const int rb = half * 32;
        int idr[32];
        #pragma unroll
        for (int r = 0; r < 32; ++r)
            idr[r] = __ldg(&idp[(row0 + rb + r) * 4]);
        #pragma unroll
        for (int r = 0; r < 32; ++r)
            Xs[(rb + r) * XSTR + c] = tf32f(__ldg(&tf[(size_t)idr[r] * EMBDIM]));
    }

    // ================ GEMM1: H[64,256] = relu(X @ W1 + b1) ================
    const int n0 = w8 * 32;            // warp tile 32m x 32n
    float c1[2][4][4];
    #pragma unroll
    for (int mt = 0; mt < 2; ++mt)
        #pragma unroll
        for (int u = 0; u < 4; ++u)
            #pragma unroll
            for (int i = 0; i < 4; ++i) c1[mt][u][i] = 0.f;

    #pragma unroll 1
    for (int tt = 0; tt < 8; ++tt) {
        CP_WAIT_ALL();
        __syncthreads();
        if (tt < 7) {
            float* wn = (tt & 1) ? Wb0 : Wb1;
            const float* gsrc = W1 + (tt + 1) * 32 * 256;
            #pragma unroll
            for (int i = tid; i < 32 * 64; i += 512) {
                int kr = i >> 6, f4 = (i & 63) << 2;
                cp16(&wn[kr * W1STR + f4], &gsrc[kr * 256 + f4]);
            }
            CP_COMMIT();
        }
        const float* ws = (tt & 1) ? Wb1 : Wb0;
        #pragma unroll
        for (int ks = 0; ks < 4; ++ks) {               // k8-steps within tile
            const int kk = tt * 32 + ks * 8;
            unsigned a[2][4];
            #pragma unroll
            for (int mt = 0; mt < 2; ++mt) {
                const float* xr = Xs + (mbase + mt * 16 + g) * XSTR + kk + t4;
                a[mt][0] = __float_as_uint(xr[0]);
                a[mt][1] = __float_as_uint(xr[8 * XSTR]);
                a[mt][2] = __float_as_uint(xr[4]);
                a[mt][3] = __float_as_uint(xr[8 * XSTR + 4]);
            }
            const float* wk = ws + (ks * 8 + t4) * W1STR + n0 + g;
            #pragma unroll
            for (int u = 0; u < 4; ++u) {
                // raw fp32 bits: HMMA reads the tf32 field (RZ-truncated W)
                unsigned b0  = __float_as_uint(wk[8 * u]);
                unsigned b1r = __float_as_uint(wk[4 * W1STR + 8 * u]);
                #pragma unroll
                for (int mt = 0; mt < 2; ++mt)
                    MMA_TF32(c1[mt][u], a[mt], b0, b1r);
            }
        }
    }

    // Launch W2 tile 0 (32x128) into Wb0 (tile 6 fully consumed by all warps)
    #pragma unroll
    for (int i = tid; i < 32 * 32; i += 512) {
        int kr = i >> 5, f4 = (i & 31) << 2;
        cp16(&Wb0[kr * W2STR + f4], &W2[kr * 128 + f4]);
    }
    CP_COMMIT();
    __syncthreads();       // everyone done reading X before overwrite

    // bias + relu, H (tf32) back into Xs
    #pragma unroll
    for (int u = 0; u < 4; ++u) {
        int col0 = n0 + 8 * u + 2 * t4;
        float2 bb = *(const float2*)&b1[col0];
        #pragma unroll
        for (int mt = 0; mt < 2; ++mt) {
            int r = mbase + mt * 16 + g;
            float2 h0, h1;
            h0.x = tf32f(fmaxf(c1[mt][u][0] + bb.x, 0.f));
            h0.y = tf32f(fmaxf(c1[mt][u][1] + bb.y, 0.f));
            h1.x = tf32f(fmaxf(c1[mt][u][2] + bb.x, 0.f));
            h1.y = tf32f(fmaxf(c1[mt][u][3] + bb.y, 0.f));
            *(float2*)&Xs[r * XSTR + col0]       = h0;
            *(float2*)&Xs[(r + 8) * XSTR + col0] = h1;
        }
    }

    // ================ GEMM2: U[64,128] = relu(H @ W2 + b2) ================
    const int n02 = w8 * 16;           // warp tile 32m x 16n
    float c2[2][2][4];
    #pragma unroll
    for (int mt = 0; mt < 2; ++mt)
        #pragma unroll
        for (int u = 0; u < 2; ++u)
            #pragma unroll
            for (int i = 0; i < 4; ++i) c2[mt][u][i] = 0.f;

    #pragma unroll 1
    for (int tt = 0; tt < 8; ++tt) {
        CP_WAIT_ALL();
        __syncthreads();               // tt=0 also orders H writes
        if (tt < 7) {
            float* wn = (tt & 1) ? Wb0 : Wb1;
            const float* gsrc = W2 + (tt + 1) * 32 * 128;
            #pragma unroll
            for (int i = tid; i < 32 * 32; i += 512) {
                int kr = i >> 5, f4 = (i & 31) << 2;
                cp16(&wn[kr * W2STR + f4], &gsrc[kr * 128 + f4]);
            }
            CP_COMMIT();
        }
        const float* ws = (tt & 1) ? Wb1 : Wb0;
        #pragma unroll
        for (int ks = 0; ks < 4; ++ks) {
            const int kk = tt * 32 + ks * 8;
            unsigned a[2][4];
            #pragma unroll
            for (int mt = 0; mt < 2; ++mt) {
                const float* xr = Xs + (mbase + mt * 16 + g) * XSTR + kk + t4;
                a[mt][0] = __float_as_uint(xr[0]);
                a[mt][1] = __float_as_uint(xr[8 * XSTR]);
                a[mt][2] = __float_as_uint(xr[4]);
                a[mt][3] = __float_as_uint(xr[8 * XSTR + 4]);
            }
            const float* wk = ws + (ks * 8 + t4) * W2STR + n02 + g;
            #pragma unroll
            for (int u = 0; u < 2; ++u) {
                unsigned b0  = __float_as_uint(wk[8 * u]);
                unsigned b1r = __float_as_uint(wk[4 * W2STR + 8 * u]);
                #pragma unroll
                for (int mt = 0; mt < 2; ++mt)
                    MMA_TF32(c2[mt][u], a[mt], b0, b1r);
            }
        }
    }

    // ---- Epilogue: bias + relu into U staging (Wb0), then row-normalize ----
    float* Us = Wb0;                   // safe: Wb0 last read at tile 6, barrier passed
    #pragma unroll
    for (int u = 0; u < 2; ++u) {
        int col0 = n02 + 8 * u + 2 * t4;
        float2 bb = *(const float2*)&b2[col0];
        #pragma unroll
        for (int mt = 0; mt < 2; ++mt) {
            int r = mbase + mt * 16 + g;
            Us[r * USTR + col0]           = fmaxf(c2[mt][u][0] + bb.x, 0.f);
            Us[r * USTR + col0 + 1]       = fmaxf(c2[mt][u][1] + bb.y, 0.f);
            Us[(r + 8) * USTR + col0]     = fmaxf(c2[mt][u][2] + bb.x, 0.f);
            Us[(r + 8) * USTR + col0 + 1] = fmaxf(c2[mt][u][3] + bb.y, 0.f);
        }
    }
    __syncthreads();

    // Normalize: thread handles row r = tid>>3, cols q*16..q*16+15
    {
        const int r = tid >> 3, q = tid & 7;
        const float* ur = Us + r * USTR + q * 16;
        float v[16];
        float sq = 0.f;
        #pragma unroll
        for (int i = 0; i < 16; ++i) { v[i] = ur[i]; sq = fmaf(v[i], v[i], sq); }
        sq += __shfl_xor_sync(0xffffffffu, sq, 1);
        sq += __shfl_xor_sync(0xffffffffu, sq, 2);
        sq += __shfl_xor_sync(0xffffffffu, sq, 4);
        float inv = 1.f / fmaxf(sqrtf(sq), 1e-8f);
        float* go = gout + (size_t)(row0 + r) * D_OUT + q * 16;
        #pragma unroll
        for (int i = 0; i < 4; ++i) {
            float4 o = make_float4(v[4*i] * inv, v[4*i+1] * inv,
                                   v[4*i+2] * inv, v[4*i+3] * inv);
            *(float4*)&go[4 * i] = o;
        }
    }

    // ================ Device-wide barrier (all 128 CTAs co-resident) ================
    __threadfence();                   // publish g_uv (release)
    __syncthreads();                   // all threads in CTA done storing
    if (tid == 0) {
        unsigned t = atomicAdd(&g_bar, 1u);
        unsigned release = ((t >> 7) + 1u) << 7;   // next multiple of 128 above t
        while (atomicAdd(&g_bar, 0u) < release) { }
    }
    __syncthreads();
    __threadfence();                   // acquire: see all CTAs' g_uv writes

    // ================ Score phase: this block scores 32 rows ================
    // Block b -> rows sb0..sb0+31; out[row][j] = u_row . v_{(row+j)%B} - log(sw)
    {
        const int sb0 = blockIdx.x * 32;
        const int grp = lane >> 3;     // band column j
        const int l8  = lane & 7;
        const float* vnb = g_uv + (size_t)BATCH * D_OUT;

        #pragma unroll
        for (int it = 0; it < 2; ++it) {
            int row = sb0 + 2 * warp + it;                 // 16 warps x 2 rows
            int col = (row + grp) & (BATCH - 1);
            // hoist debias chain; overlaps the dot below
            float sw = __ldg(&sw_table[__ldg(&sw_ids[col])]);

            const float4* up = (const float4*)&g_uv[(size_t)row * D_OUT + l8 * 16];
            const float4* vp = (const float4*)&vnb[(size_t)col * D_OUT + l8 * 16];
            float d = 0.f;
            #pragma unroll
            for (int i = 0; i < 4; ++i) {
                float4 a = up[i], b = vp[i];
                d = fmaf(a.x, b.x, fmaf(a.y, b.y, fmaf(a.z, b.z, fmaf(a.w, b.w, d))));
            }
            d += __shfl_xor_sync(0xffffffffu, d, 1);
            d += __shfl_xor_sync(0xffffffffu, d, 2);
            d += __shfl_xor_sync(0xffffffffu, d, 4);
            if (l8 == 0)
                out[row * N_NEG4 + grp] = d - logf(sw);
        }
    }
}

extern "C" void kernel_launch(void* const* d_in, const int* in_sizes, int n_in,
                              void* d_out, int out_size)
{
    const int*   user_ids    = (const int*)  d_in[0];
    const int*   item_ids    = (const int*)  d_in[1];
    const int*   sw_ids      = (const int*)  d_in[2];
    const float* user_tables = (const float*)d_in[3];
    const float* item_tables = (const float*)d_in[4];
    const float* sw_table    = (const float*)d_in[5];
    const float* uW1 = (const float*)d_in[6];
    const float* ub1 = (const float*)d_in[7];
    const float* uW2 = (const float*)d_in[8];
    const float* ub2 = (const float*)d_in[9];
    const float* iW1 = (const float*)d_in[10];
    const float* ib1 = (const float*)d_in[11];
    const float* iW2 = (const float*)d_in[12];
    const float* ib2 = (const float*)d_in[13];
    (void)in_sizes; (void)n_in; (void)out_size;

    const int smem_bytes = SMEM_FLOATS * (int)sizeof(float);   // 134,144 B
    cudaFuncSetAttribute(fused_kernel, cudaFuncAttributeMaxDynamicSharedMemorySize,
                         smem_bytes);

    fused_kernel<<<128, 512, smem_bytes>>>(user_ids, item_ids,
                                           user_tables, item_tables,
                                           uW1, ub1, uW2, ub2,
                                           iW1, ib1, iW2, ib2,
                                           sw_ids, sw_table, (float*)d_out);
}

// round 17
// speedup vs baseline: 1.1204x; 1.1204x over previous
#include <cuda_runtime.h>
#include <math.h>

// Problem constants
#define BATCH   4096
#define VOCABSZ 100000
#define EMBDIM  64
#define D_IN    256
#define D_H     256
#define D_OUT   128
#define N_NEG4  4

// Scratch: NORMALIZED tower outputs (u then v)
__device__ float g_uv[2u * BATCH * D_OUT];

// Tiling: TM=32 rows/CTA -> ~98.5 KB smem -> 2 CTAs/SM (independent stall domains)
constexpr int TM    = 32;
constexpr int XSTR  = 260;   // X/H smem row stride (floats): conflict-free fragment loads
constexpr int W1STR = 264;   // W1 tile stride
constexpr int W2STR = 136;   // W2 tile stride
constexpr int USTR  = 129;   // U staging stride
constexpr int XS_FLOATS   = TM * XSTR;            // 8320
constexpr int WBUF_FLOATS = 32 * W1STR;           // 8448
constexpr int SMEM_FLOATS = XS_FLOATS + 2 * WBUF_FLOATS;   // 25216 fl = 100864 B

__device__ __forceinline__ unsigned f2tf32(float f) {
    unsigned r; asm("cvt.rna.tf32.f32 %0, %1;" : "=r"(r) : "f"(f)); return r;
}
__device__ __forceinline__ float tf32f(float f) { return __uint_as_float(f2tf32(f)); }

#define MMA_TF32(c, a, b0, b1)                                              \
    asm volatile("mma.sync.aligned.m16n8k8.row.col.f32.tf32.tf32.f32 "      \
        "{%0,%1,%2,%3}, {%4,%5,%6,%7}, {%8,%9}, {%0,%1,%2,%3};"             \
        : "+f"((c)[0]), "+f"((c)[1]), "+f"((c)[2]), "+f"((c)[3])            \
        : "r"((a)[0]), "r"((a)[1]), "r"((a)[2]), "r"((a)[3]),               \
          "r"(b0), "r"(b1))

__device__ __forceinline__ void cp16(float* s, const float* g) {
    unsigned saddr = (unsigned)__cvta_generic_to_shared(s);
    asm volatile("cp.async.cg.shared.global [%0], [%1], 16;" :: "r"(saddr), "l"(g));
}
#define CP_COMMIT()   asm volatile("cp.async.commit_group;" ::: "memory")
#define CP_WAIT_ALL() asm volatile("cp.async.wait_group 0;" ::: "memory")

__global__ __launch_bounds__(256, 2)
void tower_kernel(const int* __restrict__ user_ids, const int* __restrict__ item_ids,
                  const float* __restrict__ user_tables, const float* __restrict__ item_tables,
                  const float* __restrict__ uW1, const float* __restrict__ ub1,
                  const float* __restrict__ uW2, const float* __restrict__ ub2,
                  const float* __restrict__ iW1, const float* __restrict__ ib1,
                  const float* __restrict__ iW2, const float* __restrict__ ib2)
{
    extern __shared__ float smem[];
    float* Xs  = smem;                 // X then H, [32][XSTR], tf32 bit patterns
    float* Wb0 = smem + XS_FLOATS;     // W tile double buffers / U staging
    float* Wb1 = Wb0 + WBUF_FLOATS;

    const int tower  = blockIdx.x >> 7;      // 0 = user, 1 = item
    const int rowblk = blockIdx.x & 127;     // 128 row-blocks of 32

    const int*   ids = tower ? item_ids    : user_ids;
    const float* tbl = tower ? item_tables : user_tables;
    const float* W1  = tower ? iW1 : uW1;
    const float* b1  = tower ? ib1 : ub1;
    const float* W2  = tower ? iW2 : uW2;
    const float* b2  = tower ? ib2 : ub2;
    float* gout = g_uv + (size_t)tower * BATCH * D_OUT;

    const int tid  = threadIdx.x;      // 256 threads = 8 warps
    const int warp = tid >> 5;
    const int lane = tid & 31;
    const int g    = lane >> 2;        // 0..7
    const int t4   = lane & 3;         // 0..3
    const int row0 = rowblk * TM;

    // ---- Prologue: launch W1 tile 0 (32x256) into Wb0 ----
    #pragma unroll
    for (int i = tid; i < 32 * 64; i += 256) {
        int kr = i >> 6, f4 = (i & 63) << 2;
        cp16(&Wb0[kr * W1STR + f4], &W1[kr * 256 + f4]);
    }
    CP_COMMIT();

    // ---- Embedding gather: ids to registers first (MLP), then independent table LDGs ----
    {
        const int f = tid >> 6, e = tid & 63;          // column c = tid
        const float* tf = tbl + (size_t)f * VOCABSZ * EMBDIM + e;
        const int* idp = ids + f;
        int idr[32];
        #pragma unroll
        for (int r = 0; r < 32; ++r)
            idr[r] = __ldg(&idp[(row0 + r) * 4]);
        #pragma unroll
        for (int r = 0; r < 32; ++r)
            Xs[r * XSTR + tid] = tf32f(__ldg(&tf[(size_t)idr[r] * EMBDIM]));
    }

    // ================ GEMM1: H[32,256] = relu(X @ W1 + b1) ================
    const int n0 = warp * 32;          // warp tile 32m x 32n
    float c1[2][4][4];
    #pragma unroll
    for (int mt = 0; mt < 2; ++mt)
        #pragma unroll
        for (int u = 0; u < 4; ++u)
            #pragma unroll
            for (int i = 0; i < 4; ++i) c1[mt][u][i] = 0.f;

    #pragma unroll 1
    for (int tt = 0; tt < 8; ++tt) {
        CP_WAIT_ALL();
        __syncthreads();
        if (tt < 7) {
            float* wn = (tt & 1) ? Wb0 : Wb1;
            const float* gsrc = W1 + (tt + 1) * 32 * 256;
            #pragma unroll
            for (int i = tid; i < 32 * 64; i += 256) {
                int kr = i >> 6, f4 = (i & 63) << 2;
                cp16(&wn[kr * W1STR + f4], &gsrc[kr * 256 + f4]);
            }
            CP_COMMIT();
        }
        const float* ws = (tt & 1) ? Wb1 : Wb0;
        #pragma unroll
        for (int ks = 0; ks < 4; ++ks) {               // k8-steps within tile
            const int kk = tt * 32 + ks * 8;
            unsigned a[2][4];
            #pragma unroll
            for (int mt = 0; mt < 2; ++mt) {
                const float* xr = Xs + (mt * 16 + g) * XSTR + kk + t4;
                a[mt][0] = __float_as_uint(xr[0]);
                a[mt][1] = __float_as_uint(xr[8 * XSTR]);
                a[mt][2] = __float_as_uint(xr[4]);
                a[mt][3] = __float_as_uint(xr[8 * XSTR + 4]);
            }
            const float* wk = ws + (ks * 8 + t4) * W1STR + n0 + g;
            #pragma unroll
            for (int u = 0; u < 4; ++u) {
                // raw fp32 bits: HMMA reads the tf32 field (RZ-truncated W)
                unsigned b0  = __float_as_uint(wk[8 * u]);
                unsigned b1r = __float_as_uint(wk[4 * W1STR + 8 * u]);
                #pragma unroll
                for (int mt = 0; mt < 2; ++mt)
                    MMA_TF32(c1[mt][u], a[mt], b0, b1r);
            }
        }
    }

    // Launch W2 tile 0 (32x128) into Wb0 (tile 6 fully consumed by all warps)
    #pragma unroll
    for (int i = tid; i < 32 * 32; i += 256) {
        int kr = i >> 5, f4 = (i & 31) << 2;
        cp16(&Wb0[kr * W2STR + f4], &W2[kr * 128 + f4]);
    }
    CP_COMMIT();
    __syncthreads();       // everyone done reading X before overwrite

    // bias + relu, H (tf32) back into Xs
    #pragma unroll
    for (int u = 0; u < 4; ++u) {
        int col0 = n0 + 8 * u + 2 * t4;
        float2 bb = *(const float2*)&b1[col0];
        #pragma unroll
        for (int mt = 0; mt < 2; ++mt) {
            int r = mt * 16 + g;
            float2 h0, h1;
            h0.x = tf32f(fmaxf(c1[mt][u][0] + bb.x, 0.f));
            h0.y = tf32f(fmaxf(c1[mt][u][1] + bb.y, 0.f));
            h1.x = tf32f(fmaxf(c1[mt][u][2] + bb.x, 0.f));
            h1.y = tf32f(fmaxf(c1[mt][u][3] + bb.y, 0.f));
            *(float2*)&Xs[r * XSTR + col0]       = h0;
            *(float2*)&Xs[(r + 8) * XSTR + col0] = h1;
        }
    }

    // ================ GEMM2: U[32,128] = relu(H @ W2 + b2) ================
    const int n02 = warp * 16;         // warp tile 32m x 16n
    float c2[2][2][4];
    #pragma unroll
    for (int mt = 0; mt < 2; ++mt)
        #pragma unroll
        for (int u = 0; u < 2; ++u)
            #pragma unroll
            for (int i = 0; i < 4; ++i) c2[mt][u][i] = 0.f;

    #pragma unroll 1
    for (int tt = 0; tt < 8; ++tt) {
        CP_WAIT_ALL();
        __syncthreads();               // tt=0 also orders H writes
        if (tt < 7) {
            float* wn = (tt & 1) ? Wb0 : Wb1;
            const float* gsrc = W2 + (tt + 1) * 32 * 128;
            #pragma unroll
            for (int i = tid; i < 32 * 32; i += 256) {
                int kr = i >> 5, f4 = (i & 31) << 2;
                cp16(&wn[kr * W2STR + f4], &gsrc[kr * 128 + f4]);
            }
            CP_COMMIT();
        }
        const float* ws = (tt & 1) ? Wb1 : Wb0;
        #pragma unroll
        for (int ks = 0; ks < 4; ++ks) {
            const int kk = tt * 32 + ks * 8;
            unsigned a[2][4];
            #pragma unroll
            for (int mt = 0; mt < 2; ++mt) {
                const float* xr = Xs + (mt * 16 + g) * XSTR + kk + t4;
                a[mt][0] = __float_as_uint(xr[0]);
                a[mt][1] = __float_as_uint(xr[8 * XSTR]);
                a[mt][2] = __float_as_uint(xr[4]);
                a[mt][3] = __float_as_uint(xr[8 * XSTR + 4]);
            }
            const float* wk = ws + (ks * 8 + t4) * W2STR + n02 + g;
            #pragma unroll
            for (int u = 0; u < 2; ++u) {
                unsigned b0  = __float_as_uint(wk[8 * u]);
                unsigned b1r = __float_as_uint(wk[4 * W2STR + 8 * u]);
                #pragma unroll
                for (int mt = 0; mt < 2; ++mt)
                    MMA_TF32(c2[mt][u], a[mt], b0, b1r);
            }
        }
    }

    // ---- Epilogue: bias + relu into U staging (Wb0), then row-normalize ----
    float* Us = Wb0;                   // safe: Wb0 last read at tile 6, barrier passed
    #pragma unroll
    for (int u = 0; u < 2; ++u) {
        int col0 = n02 + 8 * u + 2 * t4;
        float2 bb = *(const float2*)&b2[col0];
        #pragma unroll
        for (int mt = 0; mt < 2; ++mt) {
            int r = mt * 16 + g;
            Us[r * USTR + col0]           = fmaxf(c2[mt][u][0] + bb.x, 0.f);
            Us[r * USTR + col0 + 1]       = fmaxf(c2[mt][u][1] + bb.y, 0.f);
            Us[(r + 8) * USTR + col0]     = fmaxf(c2[mt][u][2] + bb.x, 0.f);
            Us[(r + 8) * USTR + col0 + 1] = fmaxf(c2[mt][u][3] + bb.y, 0.f);
        }
    }
    __syncthreads();

    // Normalize: thread handles row r = tid>>3 (0..31), cols q*16..q*16+15
    {
        const int r = tid >> 3, q = tid & 7;
        const float* ur = Us + r * USTR + q * 16;
        float v[16];
        float sq = 0.f;
        #pragma unroll
        for (int i = 0; i < 16; ++i) { v[i] = ur[i]; sq = fmaf(v[i], v[i], sq); }
        sq += __shfl_xor_sync(0xffffffffu, sq, 1);
        sq += __shfl_xor_sync(0xffffffffu, sq, 2);
        sq += __shfl_xor_sync(0xffffffffu, sq, 4);
        float inv = 1.f / fmaxf(sqrtf(sq), 1e-8f);
        float* go = gout + (size_t)(row0 + r) * D_OUT + q * 16;
        #pragma unroll
        for (int i = 0; i < 4; ++i) {
            float4 o = make_float4(v[4*i] * inv, v[4*i+1] * inv,
                                   v[4*i+2] * inv, v[4*i+3] * inv);
            *(float4*)&go[4 * i] = o;
        }
    }
}

// ---------------- Scoring: one warp per output element (best measured: 7.1us) ----------------
__global__ __launch_bounds__(256)
void score_kernel(const int* __restrict__ sw_ids, const float* __restrict__ sw_table,
                  float* __restrict__ out)
{
    int w    = (blockIdx.x * 256 + threadIdx.x) >> 5;   // output index 0..16383
    int lane = threadIdx.x & 31;
    int row  = w >> 2, j = w & 3;
    int col  = (row + j) & (BATCH - 1);

    // start the 2-deep debias chain first (broadcast loads, overlaps the dot)
    float lsw = logf(__ldg(&sw_table[__ldg(&sw_ids[col])]));

    float4 a = *(const float4*)&g_uv[(size_t)row * D_OUT + lane * 4];
    float4 b = *(const float4*)&g_uv[(size_t)BATCH * D_OUT
                                     + (size_t)col * D_OUT + lane * 4];
    float d = fmaf(a.x, b.x, fmaf(a.y, b.y, fmaf(a.z, b.z, a.w * b.w)));
    #pragma unroll
    for (int o = 16; o; o >>= 1) d += __shfl_xor_sync(0xffffffffu, d, o);

    if (lane == 0)
        out[w] = d - lsw;
}

extern "C" void kernel_launch(void* const* d_in, const int* in_sizes, int n_in,
                              void* d_out, int out_size)
{
    const int*   user_ids    = (const int*)  d_in[0];
    const int*   item_ids    = (const int*)  d_in[1];
    const int*   sw_ids      = (const int*)  d_in[2];
    const float* user_tables = (const float*)d_in[3];
    const float* item_tables = (const float*)d_in[4];
    const float* sw_table    = (const float*)d_in[5];
    const float* uW1 = (const float*)d_in[6];
    const float* ub1 = (const float*)d_in[7];
    const float* uW2 = (const float*)d_in[8];
    const float* ub2 = (const float*)d_in[9];
    const float* iW1 = (const float*)d_in[10];
    const float* ib1 = (const float*)d_in[11];
    const float* iW2 = (const float*)d_in[12];
    const float* ib2 = (const float*)d_in[13];
    (void)in_sizes; (void)n_in; (void)out_size;

    const int smem_bytes = SMEM_FLOATS * (int)sizeof(float);   // 100,864 B
    cudaFuncSetAttribute(tower_kernel, cudaFuncAttributeMaxDynamicSharedMemorySize,
                         smem_bytes);

    // 128 row-blocks x 2 towers = 256 CTAs, 2 per SM
    tower_kernel<<<256, 256, smem_bytes>>>(user_ids, item_ids,
                                           user_tables, item_tables,
                                           uW1, ub1, uW2, ub2,
                                           iW1, ib1, iW2, ib2);
    // 16384 warps = 2048 blocks x 8 warps
    score_kernel<<<2048, 256>>>(sw_ids, sw_table, (float*)d_out);
}